// round 5
// baseline (speedup 1.0000x reference)
#include <cuda_runtime.h>

#define C 32
#define H 128
#define W 256
#define CPB 64       // columns per block (w-split x4)
#define YROWS 129    // local jj rows: jj = w0 + r, r in [0,128]
#define YS 36        // y_sh row stride (floats); chunk stride 9 == 1 mod 8 -> conflict-free
#define GO 66
#define GS 67        // bank stride 3 mod 32 -> conflict-free
#define GROWS 65     // rows 0..63 real, row 64 = pad for boundary b-stores
#define NT 256

typedef unsigned long long u64;

__device__ __forceinline__ u64 pack2(float lo, float hi) {
    u64 r; asm("mov.b64 %0, {%1, %2};" : "=l"(r) : "f"(lo), "f"(hi)); return r;
}
__device__ __forceinline__ void ffma2(u64& acc, u64 a, u64 b) {
    asm("fma.rn.f32x2 %0, %1, %2, %0;" : "+l"(acc) : "l"(a), "l"(b));
}
__device__ __forceinline__ u64 add2(u64 a, u64 b) {
    u64 r; asm("add.rn.f32x2 %0, %1, %2;" : "=l"(r) : "l"(a), "l"(b)); return r;
}
__device__ __forceinline__ float hadd2(u64 v) {
    float lo, hi; asm("mov.b64 {%0, %1}, %2;" : "=f"(lo), "=f"(hi) : "l"(v)); return lo + hi;
}

__global__ __launch_bounds__(NT, 4)
void cost_volume_kernel(const float* __restrict__ x, const float* __restrict__ y,
                        const float* __restrict__ disp, float* __restrict__ out,
                        int D) {
    __shared__ float y_sh[YROWS * YS];   // [local jj][c]; jj = w0 + r; y col j = jj - 64
    __shared__ float G_sh[GROWS * GS];   // banded Gram, local rows

    const int blk = blockIdx.x;
    const int bh = blk >> 2;
    const int s = blk & 3;
    const int w0 = s * CPB;
    const int b = bh / H;
    const int h = bh - b * H;
    const int tid = threadIdx.x;
    const size_t HW = (size_t)H * W;
    const float* ybase = y + ((size_t)b * C * H + h) * W;
    const float* xbase = x + ((size_t)b * C * H + h) * W;

    // ---- Phase 1: stage y columns [w0-64, w0+64] transposed into smem.
    // Out-of-range columns are stored as zeros (implements the reference's
    // zero-padding boundary mask).
    if (tid < YROWS) {
        int j = w0 - 64 + tid;               // global y column
        float* dst = y_sh + tid * YS;
        if (j >= 0 && j < W) {
            const float* src = ybase + j;
            #pragma unroll
            for (int c = 0; c < C; c += 4) {
                float v0 = src[(size_t)(c + 0) * HW];
                float v1 = src[(size_t)(c + 1) * HW];
                float v2 = src[(size_t)(c + 2) * HW];
                float v3 = src[(size_t)(c + 3) * HW];
                *(float4*)(dst + c) = make_float4(v0, v1, v2, v3);
            }
        } else {
            #pragma unroll
            for (int c = 0; c < C; c += 4)
                *(float4*)(dst + c) = make_float4(0.f, 0.f, 0.f, 0.f);
        }
    }

    // Thread layout: warp = 8 columns x 4 channel-quarters.
    const int lane = tid & 31;
    const int q = lane >> 3;            // channel quarter: c in [8q, 8q+8)
    const int wl = ((tid >> 5) << 3) | (lane & 7);   // local column 0..63
    const int w = w0 + wl;              // global column
    const int cbase = q * 8;
    const bool has_b = (w + 1 < W);

    // x columns w, w+1 for this thread's 8 channels, packed for FFMA2.
    u64 xa[4], xb[4];
    #pragma unroll
    for (int k = 0; k < 4; k++) {
        float a0 = xbase[(size_t)(cbase + 2 * k) * HW + w];
        float a1 = xbase[(size_t)(cbase + 2 * k + 1) * HW + w];
        xa[k] = pack2(a0, a1);
        float b0 = has_b ? xbase[(size_t)(cbase + 2 * k) * HW + w + 1] : 0.f;
        float b1 = has_b ? xbase[(size_t)(cbase + 2 * k + 1) * HW + w + 1] : 0.f;
        xb[k] = pack2(b0, b1);
    }
    __syncthreads();

    // ---- Phase 2: banded Gram  G[w][o] = sum_c x[c][w] * y_sh[wl+o][c]
    // Anti-diagonal pairing: (w, o0) and (w+1, o0-1) share local row wl+o0.
    // Quarter partial sums combined via shfl_xor(8) + shfl_xor(16).
    const float* yrow = y_sh + wl * YS + cbase;
    #pragma unroll 1
    for (int o0 = 1; o0 <= 65; o0 += 2) {
        const ulonglong2* yp = (const ulonglong2*)(yrow + o0 * YS);
        ulonglong2 p0 = yp[0];
        ulonglong2 p1 = yp[1];
        u64 a0 = 0, a1 = 0, b0 = 0, b1 = 0;
        ffma2(a0, xa[0], p0.x);  ffma2(b0, xb[0], p0.x);
        ffma2(a1, xa[1], p0.y);  ffma2(b1, xb[1], p0.y);
        ffma2(a0, xa[2], p1.x);  ffma2(b0, xb[2], p1.x);
        ffma2(a1, xa[3], p1.y);  ffma2(b1, xb[3], p1.y);
        float av = hadd2(add2(a0, a1));
        float bv = hadd2(add2(b0, b1));
        av += __shfl_xor_sync(0xFFFFFFFFu, av, 8);
        av += __shfl_xor_sync(0xFFFFFFFFu, av, 16);
        bv += __shfl_xor_sync(0xFFFFFFFFu, bv, 8);
        bv += __shfl_xor_sync(0xFFFFFFFFu, bv, 16);
        if (q == 0)      G_sh[wl * GS + o0] = av;          // (w, odd o)
        else if (q == 1) G_sh[(wl + 1) * GS + (o0 - 1)] = bv;  // (w+1, even o); wl=63 -> pad row
    }
    // Cleanup: entries (w0, even o), 33 of them (local G row 0).
    if (tid < 33) {
        int o = 2 * tid;
        float ssum = 0.f;
        #pragma unroll
        for (int c = 0; c < C; c++)
            ssum = fmaf(xbase[(size_t)c * HW + w0], y_sh[o * YS + c], ssum);
        G_sh[o] = ssum;
    }

    // ---- Phase 3 prologue: disp loads issued before the barrier.
    const float* dbase = disp + ((size_t)b * D * H + h) * W + w0;
    float* obase = out + ((size_t)b * D * H + h) * W + w0;

    if (D == 48) {
        float4 dv[3];
        #pragma unroll
        for (int k = 0; k < 3; k++) {
            int i = tid + k * NT;           // i in [0, 768)
            int d = i >> 4;                 // 16 float4 per d (64 cols)
            int w4 = (i & 15) << 2;         // local col of float4
            dv[k] = *(const float4*)(dbase + (size_t)d * HW + w4);
        }
        __syncthreads();
        #pragma unroll
        for (int k = 0; k < 3; k++) {
            int i = tid + k * NT;
            int d = i >> 4;
            int w4 = (i & 15) << 2;
            float4 res;
            #pragma unroll
            for (int j = 0; j < 4; j++) {
                int wwl = w4 + j;               // local col
                int wwg = w0 + wwl;             // global col
                float dvj = (&dv[k].x)[j];
                float px = (float)wwg - dvj;
                float x0f = floorf(px);
                float fx = px - x0f;
                int o = (int)x0f - wwg + 64;
                float g0 = ((unsigned)o < GO) ? G_sh[wwl * GS + o] : 0.f;
                float g1 = ((unsigned)(o + 1) < GO) ? G_sh[wwl * GS + o + 1] : 0.f;
                (&res.x)[j] = (g0 + (g1 - g0) * fx) * (1.0f / C);
            }
            *(float4*)(obase + (size_t)d * HW + w4) = res;
        }
    } else {
        __syncthreads();
        const int total4 = D * (CPB / 4);
        for (int i = tid; i < total4; i += NT) {
            int d = i >> 4;
            int w4 = (i & 15) << 2;
            float4 dvv = *(const float4*)(dbase + (size_t)d * HW + w4);
            float4 res;
            #pragma unroll
            for (int j = 0; j < 4; j++) {
                int wwl = w4 + j;
                int wwg = w0 + wwl;
                float dvj = (&dvv.x)[j];
                float px = (float)wwg - dvj;
                float x0f = floorf(px);
                float fx = px - x0f;
                int o = (int)x0f - wwg + 64;
                float g0 = ((unsigned)o < GO) ? G_sh[wwl * GS + o] : 0.f;
                float g1 = ((unsigned)(o + 1) < GO) ? G_sh[wwl * GS + o + 1] : 0.f;
                (&res.x)[j] = (g0 + (g1 - g0) * fx) * (1.0f / C);
            }
            *(float4*)(obase + (size_t)d * HW + w4) = res;
        }
    }
}

extern "C" void kernel_launch(void* const* d_in, const int* in_sizes, int n_in,
                              void* d_out, int out_size) {
    const float* x = (const float*)d_in[0];
    const float* y = (const float*)d_in[1];
    const float* disp = (const float*)d_in[2];
    int B = in_sizes[0] / (C * H * W);
    int D = in_sizes[2] / (B * H * W);
    cost_volume_kernel<<<B * H * 4, NT>>>(x, y, disp, (float*)d_out, D);
}

// round 6
// speedup vs baseline: 1.3994x; 1.3994x over previous
#include <cuda_runtime.h>

#define C 32
#define H 128
#define W 256
#define YS 36        // y_sh row stride (144B): 16B-aligned, lane bank stride 4 -> conflict-free
#define YROWS 257    // rows 0..255 = y columns 0..255; row 256 = zero row (both boundaries)
#define GO 66
#define GS 67
#define GROWS 257    // rows 0..255 real; row 256 pads the w=255 b-store
#define NT 256

typedef unsigned long long u64;

__device__ __forceinline__ u64 pack2(float lo, float hi) {
    u64 r; asm("mov.b64 %0, {%1, %2};" : "=l"(r) : "f"(lo), "f"(hi)); return r;
}
__device__ __forceinline__ void ffma2(u64& acc, u64 a, u64 b) {
    asm("fma.rn.f32x2 %0, %1, %2, %0;" : "+l"(acc) : "l"(a), "l"(b));
}
__device__ __forceinline__ u64 add2(u64 a, u64 b) {
    u64 r; asm("add.rn.f32x2 %0, %1, %2;" : "=l"(r) : "l"(a), "l"(b)); return r;
}
__device__ __forceinline__ float hadd2(u64 v) {
    float lo, hi; asm("mov.b64 {%0, %1}, %2;" : "=f"(lo), "=f"(hi) : "l"(v)); return lo + hi;
}

__global__ __launch_bounds__(NT, 2)
void cost_volume_kernel(const float* __restrict__ x, const float* __restrict__ y,
                        const float* __restrict__ disp, float* __restrict__ out,
                        int D) {
    extern __shared__ float sm[];
    float* y_sh = sm;                  // YROWS * YS  ([col][c]; row r = y column r; row 256 = zeros)
    float* G_sh = sm + YROWS * YS;     // GROWS * GS banded Gram

    const int bh = blockIdx.x;
    const int b = bh / H;
    const int h = bh - b * H;
    const int tid = threadIdx.x;
    const size_t HW = (size_t)H * W;
    const float* ybase = y + ((size_t)b * C * H + h) * W;
    const float* xbase = x + ((size_t)b * C * H + h) * W;

    // ---- Phase 1: stage y row transposed into smem (row r = y column r).
    // Row 256 is the shared zero row implementing the reference's
    // zero-padding mask at BOTH boundaries.
    {
        const float* src = ybase + tid;          // column j = tid
        float* dst = y_sh + tid * YS;
        #pragma unroll
        for (int c = 0; c < C; c += 4) {
            float v0 = src[(size_t)(c + 0) * HW];
            float v1 = src[(size_t)(c + 1) * HW];
            float v2 = src[(size_t)(c + 2) * HW];
            float v3 = src[(size_t)(c + 3) * HW];
            *(float4*)(dst + c) = make_float4(v0, v1, v2, v3);
        }
    }
    if (tid < YS) y_sh[256 * YS + tid] = 0.0f;   // the zero row

    // x columns w and w+1, all 32 channels, packed for FFMA2.
    const int w = tid;                // blockDim.x == W
    const bool has_b = (w + 1 < W);
    u64 xa[16], xb[16];
    #pragma unroll
    for (int k = 0; k < 16; k++) {
        float a0 = xbase[(size_t)(2 * k) * HW + w];
        float a1 = xbase[(size_t)(2 * k + 1) * HW + w];
        xa[k] = pack2(a0, a1);
        float b0 = has_b ? xbase[(size_t)(2 * k) * HW + w + 1] : 0.f;
        float b1 = has_b ? xbase[(size_t)(2 * k + 1) * HW + w + 1] : 0.f;
        xb[k] = pack2(b0, b1);
    }
    __syncthreads();

    // ---- Phase 2: banded Gram  G[w][o] = sum_c x[c][w] * y[c][w+o-64]
    // Anti-diagonal pairing: (w, o0) and (w+1, o0-1) share y column w+o0-64.
    // Row clamp: r < 0 -> 256 (zero row); r == 256 (w=255,o0=65) is already
    // the zero row (y column 256 is out of range).
    float* ga = G_sh + w * GS;
    float* gb = G_sh + (w + 1) * GS;
    #pragma unroll 1
    for (int o0 = 1; o0 <= 65; o0 += 2) {
        int r = w + o0 - 64;
        if (r < 0) r = 256;
        const ulonglong2* yp = (const ulonglong2*)(y_sh + r * YS);
        ulonglong2 q0 = yp[0], q1 = yp[1], q2 = yp[2], q3 = yp[3];
        ulonglong2 q4 = yp[4], q5 = yp[5], q6 = yp[6], q7 = yp[7];
        u64 a0 = 0, a1 = 0, a2 = 0, a3 = 0;
        u64 b0 = 0, b1 = 0, b2 = 0, b3 = 0;
        ffma2(a0, xa[0],  q0.x);  ffma2(b0, xb[0],  q0.x);
        ffma2(a1, xa[1],  q0.y);  ffma2(b1, xb[1],  q0.y);
        ffma2(a2, xa[2],  q1.x);  ffma2(b2, xb[2],  q1.x);
        ffma2(a3, xa[3],  q1.y);  ffma2(b3, xb[3],  q1.y);
        ffma2(a0, xa[4],  q2.x);  ffma2(b0, xb[4],  q2.x);
        ffma2(a1, xa[5],  q2.y);  ffma2(b1, xb[5],  q2.y);
        ffma2(a2, xa[6],  q3.x);  ffma2(b2, xb[6],  q3.x);
        ffma2(a3, xa[7],  q3.y);  ffma2(b3, xb[7],  q3.y);
        ffma2(a0, xa[8],  q4.x);  ffma2(b0, xb[8],  q4.x);
        ffma2(a1, xa[9],  q4.y);  ffma2(b1, xb[9],  q4.y);
        ffma2(a2, xa[10], q5.x);  ffma2(b2, xb[10], q5.x);
        ffma2(a3, xa[11], q5.y);  ffma2(b3, xb[11], q5.y);
        ffma2(a0, xa[12], q6.x);  ffma2(b0, xb[12], q6.x);
        ffma2(a1, xa[13], q6.y);  ffma2(b1, xb[13], q6.y);
        ffma2(a2, xa[14], q7.x);  ffma2(b2, xb[14], q7.x);
        ffma2(a3, xa[15], q7.y);  ffma2(b3, xb[15], q7.y);
        ga[o0]     = hadd2(add2(add2(a0, a1), add2(a2, a3)));
        gb[o0 - 1] = hadd2(add2(add2(b0, b1), add2(b2, b3)));
    }
    // Cleanup: entries (w=0, even o). For o < 64 the sample column o-64 is
    // out of range -> 0. o == 64 is the single real entry: y column 0.
    if (tid < 33) {
        int o = 2 * tid;
        float s = 0.f;
        if (o == 64) {
            #pragma unroll
            for (int c = 0; c < C; c++)
                s = fmaf(xbase[(size_t)c * HW], y_sh[0 * YS + c], s);
        }
        G_sh[o] = s;
    }

    // ---- Phase 3 prologue: issue all disp loads BEFORE the barrier so their
    // gmem latency hides under other warps' phase-2 tail.
    const float* dbase = disp + ((size_t)b * D * H + h) * W;
    float* obase = out + ((size_t)b * D * H + h) * W;

    if (D == 48) {
        float4 dv[12];
        #pragma unroll
        for (int k = 0; k < 12; k++) {
            int i = tid + k * NT;
            int d = i >> 6;               // W/4 == 64
            int w4 = (i & 63) << 2;
            dv[k] = *(const float4*)(dbase + (size_t)d * HW + w4);
        }
        __syncthreads();
        #pragma unroll
        for (int k = 0; k < 12; k++) {
            int i = tid + k * NT;
            int d = i >> 6;
            int w4 = (i & 63) << 2;
            float4 res;
            #pragma unroll
            for (int j = 0; j < 4; j++) {
                int ww = w4 + j;
                float dvj = (&dv[k].x)[j];
                float px = (float)ww - dvj;
                float x0f = floorf(px);
                float fx = px - x0f;
                int o = (int)x0f - ww + 64;
                float g0 = ((unsigned)o < GO) ? G_sh[ww * GS + o] : 0.f;
                float g1 = ((unsigned)(o + 1) < GO) ? G_sh[ww * GS + o + 1] : 0.f;
                (&res.x)[j] = (g0 + (g1 - g0) * fx) * (1.0f / C);
            }
            *(float4*)(obase + (size_t)d * HW + w4) = res;
        }
    } else {
        __syncthreads();
        const int total4 = D * (W / 4);
        #pragma unroll 4
        for (int i = tid; i < total4; i += NT) {
            int d = i >> 6;
            int w4 = (i & 63) << 2;
            float4 dvv = *(const float4*)(dbase + (size_t)d * HW + w4);
            float4 res;
            #pragma unroll
            for (int j = 0; j < 4; j++) {
                int ww = w4 + j;
                float dvj = (&dvv.x)[j];
                float px = (float)ww - dvj;
                float x0f = floorf(px);
                float fx = px - x0f;
                int o = (int)x0f - ww + 64;
                float g0 = ((unsigned)o < GO) ? G_sh[ww * GS + o] : 0.f;
                float g1 = ((unsigned)(o + 1) < GO) ? G_sh[ww * GS + o + 1] : 0.f;
                (&res.x)[j] = (g0 + (g1 - g0) * fx) * (1.0f / C);
            }
            *(float4*)(obase + (size_t)d * HW + w4) = res;
        }
    }
}

extern "C" void kernel_launch(void* const* d_in, const int* in_sizes, int n_in,
                              void* d_out, int out_size) {
    const float* x = (const float*)d_in[0];
    const float* y = (const float*)d_in[1];
    const float* disp = (const float*)d_in[2];
    int B = in_sizes[0] / (C * H * W);
    int D = in_sizes[2] / (B * H * W);
    int smem = (YROWS * YS + GROWS * GS) * (int)sizeof(float);
    cudaFuncSetAttribute(cost_volume_kernel,
                         cudaFuncAttributeMaxDynamicSharedMemorySize, smem);
    cost_volume_kernel<<<B * H, NT, smem>>>(x, y, disp, (float*)d_out, D);
}